// round 15
// baseline (speedup 1.0000x reference)
#include <cuda_runtime.h>
#include <cuda_fp16.h>
#include <cstdint>

constexpr int S_LEN = 2048;
constexpr int SEQ   = 4096;
constexpr int HID   = 2048;
constexpr int KDIM  = 2048;
constexpr float WSCALE = 64.0f;          // keep W's m-plane out of fp16 subnormals

// ---------------------------------------------------------------------------
// Scratch (__device__ globals; allocation-free rule)
// ---------------------------------------------------------------------------
__device__ __half g_osH[(size_t)S_LEN * HID];
__device__ __half g_osM[(size_t)S_LEN * HID];
__device__ __half g_wtH[(size_t)HID * HID];    // wt[k][h] = 64*W[h][k]
__device__ __half g_wtM[(size_t)HID * HID];
__device__ __half g_hiH[(size_t)SEQ * HID];
__device__ __half g_hiM[(size_t)SEQ * HID];
__device__ __half g_tH[(size_t)S_LEN * HID];   // planes of T' = 64*T
__device__ __half g_tM[(size_t)S_LEN * HID];
__device__ float g_scores[(size_t)S_LEN * SEQ];
// work-queue state (memset to 0 by host each launch)
__device__ unsigned int g_qhead;
__device__ unsigned int g_histdone;
__device__ unsigned int g_done1[16];

// ---------------------------------------------------------------------------
// PTX helpers (sm_80-baseline features only: legal on .target sm_103)
// ---------------------------------------------------------------------------
__device__ __forceinline__ uint32_t smem_to_u32(const void* p) {
    uint32_t a;
    asm("{ .reg .u64 t; cvta.to.shared.u64 t, %1; cvt.u32.u64 %0, t; }" : "=r"(a) : "l"(p));
    return a;
}
__device__ __forceinline__ void cp16(uint32_t dst, const void* src) {
    asm volatile("cp.async.cg.shared.global [%0], [%1], 16;" :: "r"(dst), "l"(src));
}
__device__ __forceinline__ void cp_commit() {
    asm volatile("cp.async.commit_group;" ::: "memory");
}
template <int N>
__device__ __forceinline__ void cp_wait() {
    asm volatile("cp.async.wait_group %0;" :: "n"(N) : "memory");
}
__device__ __forceinline__ void ldm4(uint32_t* r, uint32_t addr) {
    asm volatile("ldmatrix.sync.aligned.m8n8.x4.shared.b16 {%0,%1,%2,%3}, [%4];"
                 : "=r"(r[0]), "=r"(r[1]), "=r"(r[2]), "=r"(r[3]) : "r"(addr));
}
__device__ __forceinline__ void mma16816(float* d, const uint32_t* a, const uint32_t* b) {
    asm volatile(
        "mma.sync.aligned.m16n8k16.row.col.f32.f16.f16.f32 "
        "{%0,%1,%2,%3}, {%4,%5,%6,%7}, {%8,%9}, {%0,%1,%2,%3};"
        : "+f"(d[0]), "+f"(d[1]), "+f"(d[2]), "+f"(d[3])
        : "r"(a[0]), "r"(a[1]), "r"(a[2]), "r"(a[3]), "r"(b[0]), "r"(b[1]));
}

// ---------------------------------------------------------------------------
// 2-way fp16 split helpers
// ---------------------------------------------------------------------------
__device__ __forceinline__ void split2(float a, __half& h, __half& m) {
    h = __float2half_rn(a);
    float r = a - __half2float(h);
    m = __float2half_rn(r);
}

// Merged prep: blocks [0,4096) split out_state elementwise;
//              blocks [4096,8192) transpose+scale+split W.
__global__ __launch_bounds__(256) void prep_kernel(const float* __restrict__ os,
                                                   __half* __restrict__ osH,
                                                   __half* __restrict__ osM,
                                                   const float* __restrict__ W,
                                                   __half* __restrict__ wtH,
                                                   __half* __restrict__ wtM) {
    if (blockIdx.x < 4096) {
        const int i = blockIdx.x * 256 + threadIdx.x;      // < 2048*2048/4
        float4 v = reinterpret_cast<const float4*>(os)[i];
        __half h[4], m[4];
        split2(v.x, h[0], m[0]);
        split2(v.y, h[1], m[1]);
        split2(v.z, h[2], m[2]);
        split2(v.w, h[3], m[3]);
        reinterpret_cast<__half2*>(osH)[i * 2]     = __half2{h[0], h[1]};
        reinterpret_cast<__half2*>(osH)[i * 2 + 1] = __half2{h[2], h[3]};
        reinterpret_cast<__half2*>(osM)[i * 2]     = __half2{m[0], m[1]};
        reinterpret_cast<__half2*>(osM)[i * 2 + 1] = __half2{m[2], m[3]};
    } else {
        __shared__ float tile[32][33];
        const int bid = blockIdx.x - 4096;                 // 0..4095
        const int tx = threadIdx.x & 31;
        const int ty = threadIdx.x >> 5;
        const int k0 = (bid & 63) * 32;
        const int h0 = (bid >> 6) * 32;
        #pragma unroll
        for (int j = 0; j < 32; j += 8)
            tile[ty + j][tx] = W[(size_t)(h0 + ty + j) * HID + k0 + tx];
        __syncthreads();
        #pragma unroll
        for (int j = 0; j < 32; j += 8) {
            float a = tile[tx][ty + j] * WSCALE;
            __half h, m;
            split2(a, h, m);
            size_t o = (size_t)(k0 + ty + j) * HID + h0 + tx;
            wtH[o] = h; wtM[o] = m;
        }
    }
}

// ---------------------------------------------------------------------------
// HMMA emulated-fp32 GEMM tile body: C[128,256] = A @ B^T (fp16 2-way split,
// products hh, hm, mh).  8 warps (2M x 4N), warp tile 64x64, KC=64, 2-stage.
// __noinline__: exactly ONE code copy (~32KB) so the fused kernel's hot loop
// fits I$ (R13's dual-inline copy thrashed it).
//   epi==0: split C into fp16 h/m planes     epi==1: C = C*(1/WSCALE) f32
// ---------------------------------------------------------------------------
constexpr int KC    = 64;
constexpr int NCC   = KDIM / KC;               // 32 chunks
constexpr int ROWB  = 144;                     // 128B data + 16B pad
constexpr int G_NT  = 256;
constexpr int G_RT  = 2 * (128 + G_NT);        // 768 rows per stage
constexpr int G_STG = G_RT * ROWB;             // 110592
constexpr size_t G_SMEM = (size_t)2 * G_STG;   // 221184

__device__ __noinline__ void gemm_tile(
    uint32_t sb, int rowBase, int colBase,
    const __half* __restrict__ Ah, const __half* __restrict__ Am,
    const __half* __restrict__ Bh, const __half* __restrict__ Bm,
    int epi, float* __restrict__ outF,
    __half* __restrict__ Oh, __half* __restrict__ Om, int N) {
    const int tid  = threadIdx.x;
    const int lane = tid & 31;
    const int w    = tid >> 5;
    const int wm   = w & 1;        // 2 warps along M (64 rows)
    const int wn   = w >> 1;       // 4 warps along N (64 cols)

    uint32_t aOff[4], bOff[4];
    #pragma unroll
    for (int mt = 0; mt < 4; mt++)
        aOff[mt] = (uint32_t)((wm * 64 + mt * 16 + (lane & 15)) * ROWB + ((lane >> 4) << 4));
    #pragma unroll
    for (int nb = 0; nb < 4; nb++)
        bOff[nb] = (uint32_t)((wn * 64 + nb * 16 + (lane & 7) + ((lane >> 4) << 3)) * ROWB
                              + (((lane >> 3) & 1) << 4));

    float acc[4][8][4];
    #pragma unroll
    for (int mt = 0; mt < 4; mt++)
        #pragma unroll
        for (int nt = 0; nt < 8; nt++)
            #pragma unroll
            for (int q = 0; q < 4; q++) acc[mt][nt][q] = 0.f;

    const int lr = tid >> 2;        // 0..63
    const int lc = tid & 3;         // 16B chunk pair within 128B row
    auto load_stage = [&](int kc) {
        const uint32_t dst = sb + (uint32_t)(kc & 1) * G_STG;
        const char* sA[2] = {(const char*)(Ah + (size_t)(rowBase + lr) * KDIM + kc * KC),
                             (const char*)(Am + (size_t)(rowBase + lr) * KDIM + kc * KC)};
        const char* sB[2] = {(const char*)(Bh + (size_t)(colBase + lr) * KDIM + kc * KC),
                             (const char*)(Bm + (size_t)(colBase + lr) * KDIM + kc * KC)};
        #pragma unroll
        for (int p = 0; p < 2; p++) {
            #pragma unroll
            for (int j = 0; j < 2; j++) {          // A rows lr + 64j
                const int r = lr + j * 64;
                const char* src = sA[p] + (size_t)j * 64 * KDIM * 2;
                const uint32_t d = dst + (uint32_t)((p * 128 + r) * ROWB);
                cp16(d + lc * 16, src + lc * 16);
                cp16(d + lc * 16 + 64, src + lc * 16 + 64);
            }
            #pragma unroll
            for (int j = 0; j < 4; j++) {          // B rows lr + 64j
                const int r = lr + j * 64;
                const char* src = sB[p] + (size_t)j * 64 * KDIM * 2;
                const uint32_t d = dst + (uint32_t)((256 + p * G_NT + r) * ROWB);
                cp16(d + lc * 16, src + lc * 16);
                cp16(d + lc * 16 + 64, src + lc * 16 + 64);
            }
        }
    };

    load_stage(0); cp_commit();

    for (int kc = 0; kc < NCC; kc++) {
        cp_wait<0>();
        __syncthreads();
        if (kc + 1 < NCC) load_stage(kc + 1);
        cp_commit();

        const uint32_t base = sb + (uint32_t)(kc & 1) * G_STG;
        #pragma unroll
        for (int s = 0; s < 4; s++) {              // four k16 steps per chunk
            uint32_t af[2][4][4];
            uint32_t bf[2][4][4];
            #pragma unroll
            for (int pa = 0; pa < 2; pa++)
                #pragma unroll
                for (int mt = 0; mt < 4; mt++)
                    ldm4(af[pa][mt], base + (uint32_t)(pa * 128 * ROWB) + aOff[mt] + s * 32);
            #pragma unroll
            for (int pb = 0; pb < 2; pb++)
                #pragma unroll
                for (int nb = 0; nb < 4; nb++)
                    ldm4(bf[pb][nb],
                         base + (uint32_t)((256 + pb * G_NT) * ROWB) + bOff[nb] + s * 32);
            #pragma unroll
            for (int pb = 0; pb < 2; pb++)
                #pragma unroll
                for (int pa = 0; pa < 2; pa++) {
                    if (pa + pb > 1) continue;      // hh, mh, hm
                    #pragma unroll
                    for (int mt = 0; mt < 4; mt++)
                        #pragma unroll
                        for (int nt = 0; nt < 8; nt++)
                            mma16816(acc[mt][nt], af[pa][mt],
                                     &bf[pb][nt >> 1][(nt & 1) * 2]);
                }
        }
    }

    const int g   = lane >> 2;
    const int tig = lane & 3;
    constexpr float INVS = 1.0f / WSCALE;
    #pragma unroll
    for (int mt = 0; mt < 4; mt++) {
        #pragma unroll
        for (int hh = 0; hh < 2; hh++) {
            const int row = rowBase + wm * 64 + mt * 16 + g + hh * 8;
            #pragma unroll
            for (int nt = 0; nt < 8; nt++) {
                const int col = colBase + wn * 64 + nt * 8 + tig * 2;
                const float v0 = acc[mt][nt][hh * 2];
                const float v1 = acc[mt][nt][hh * 2 + 1];
                if (epi == 0) {
                    __half h0, m0, h1, m1;
                    split2(v0, h0, m0);
                    split2(v1, h1, m1);
                    const size_t o = (size_t)row * N + col;
                    *reinterpret_cast<__half2*>(Oh + o) = __half2{h0, h1};
                    *reinterpret_cast<__half2*>(Om + o) = __half2{m0, m1};
                } else {
                    *reinterpret_cast<float2*>(outF + (size_t)row * N + col) =
                        make_float2(v0 * INVS, v1 * INVS);
                }
            }
        }
    }
}

// ---------------------------------------------------------------------------
// Fused persistent kernel: 400 work items over 148 resident CTAs.
//   items [0,16):    history split chunks (producer for gemm2 B operand)
//   items [16,144):  gemm1 tiles  T' = out_state @ (64*W)  (rb=t>>3, cb=t&7)
//   items [144,400): gemm2 tiles  scores = (T' @ hist^T)/64 (rb=t>>4, cb=t&15)
// gemm2 items gate on done1[rb]==8 && histdone==16 (release: fence+atomicAdd).
// cp.async.cg loads bypass L1, so no stale-L1 hazard on cross-SM data.
// ---------------------------------------------------------------------------
constexpr unsigned N_HIST  = 16;
constexpr unsigned N_G1    = 128;
constexpr unsigned N_G2    = 256;
constexpr unsigned N_ITEMS = N_HIST + N_G1 + N_G2;   // 400

__global__ __launch_bounds__(256, 1)
void fused_persistent(const __half* __restrict__ osH, const __half* __restrict__ osM,
                      const __half* __restrict__ wtH, const __half* __restrict__ wtM,
                      __half* __restrict__ hiH, __half* __restrict__ hiM,
                      __half* __restrict__ tH, __half* __restrict__ tM,
                      float* __restrict__ scores,
                      const float* __restrict__ hist) {
    extern __shared__ char smem[];
    const uint32_t sb = smem_to_u32(smem);
    const int tid = threadIdx.x;
    __shared__ unsigned item_s;

    for (;;) {
        if (tid == 0) item_s = atomicAdd(&g_qhead, 1u);
        __syncthreads();
        const unsigned item = item_s;
        __syncthreads();                       // item_s safe to rewrite next iter
        if (item >= N_ITEMS) return;

        if (item < N_HIST) {
            // ---- history split chunk ----
            const int n4 = SEQ * HID / 4;
            for (int i = (int)item * 256 + tid; i < n4; i += (int)N_HIST * 256) {
                float4 v = reinterpret_cast<const float4*>(hist)[i];
                __half hh[4], mm[4];
                split2(v.x, hh[0], mm[0]);
                split2(v.y, hh[1], mm[1]);
                split2(v.z, hh[2], mm[2]);
                split2(v.w, hh[3], mm[3]);
                reinterpret_cast<__half2*>(hiH)[i * 2]     = __half2{hh[0], hh[1]};
                reinterpret_cast<__half2*>(hiH)[i * 2 + 1] = __half2{hh[2], hh[3]};
                reinterpret_cast<__half2*>(hiM)[i * 2]     = __half2{mm[0], mm[1]};
                reinterpret_cast<__half2*>(hiM)[i * 2 + 1] = __half2{mm[2], mm[3]};
            }
            __threadfence();
            __syncthreads();
            if (tid == 0) atomicAdd(&g_histdone, 1u);
            continue;
        }

        if (item < N_HIST + N_G1) {
            // ---- gemm1 tile: T' = out_state @ (64*W), epilogue splits T' ----
            const unsigned t = item - N_HIST;
            const int rb = (int)(t >> 3), cb = (int)(t & 7);
            gemm_tile(sb, rb * 128, cb * G_NT, osH, osM, wtH, wtM,
                      0, nullptr, tH, tM, HID);
            __threadfence();
            __syncthreads();
            if (tid == 0) atomicAdd(&g_done1[rb], 1u);
            continue;
        }

        // ---- gemm2 tile: scores = (T' @ hist^T)/64, gated on producers ----
        {
            const unsigned t = item - N_HIST - N_G1;
            const int rb = (int)(t >> 4), cb = (int)(t & 15);
            if (tid == 0) {
                while (atomicAdd(&g_done1[rb], 0u) < 8u ||
                       atomicAdd(&g_histdone, 0u) < N_HIST)
                    __nanosleep(200);
            }
            __syncthreads();
            __threadfence();                   // acquire before reading T/hist
            gemm_tile(sb, rb * 128, cb * G_NT, tH, tM, hiH, hiM,
                      1, scores, nullptr, nullptr, SEQ);
        }
    }
}

// ---------------------------------------------------------------------------
// Row softmax over 4096 columns (bias term out_state.b cancels in softmax)
// ---------------------------------------------------------------------------
__global__ __launch_bounds__(256) void softmax_kernel(const float* __restrict__ scores,
                                                      float* __restrict__ out) {
    const int i = blockIdx.x;
    const float4* row = reinterpret_cast<const float4*>(scores + (size_t)i * SEQ);
    float4* orow = reinterpret_cast<float4*>(out + (size_t)i * SEQ);

    float4 v[4];
    float m = -1e30f;
    #pragma unroll
    for (int t = 0; t < 4; t++) {
        v[t] = row[threadIdx.x + t * 256];
        m = fmaxf(m, fmaxf(fmaxf(v[t].x, v[t].y), fmaxf(v[t].z, v[t].w)));
    }
    __shared__ float red[8];
    #pragma unroll
    for (int o = 16; o; o >>= 1) m = fmaxf(m, __shfl_xor_sync(0xffffffffu, m, o));
    if ((threadIdx.x & 31) == 0) red[threadIdx.x >> 5] = m;
    __syncthreads();
    float m_all = red[0];
    #pragma unroll
    for (int k = 1; k < 8; k++) m_all = fmaxf(m_all, red[k]);
    __syncthreads();

    float s = 0.f;
    #pragma unroll
    for (int t = 0; t < 4; t++) {
        v[t].x = __expf(v[t].x - m_all);
        v[t].y = __expf(v[t].y - m_all);
        v[t].z = __expf(v[t].z - m_all);
        v[t].w = __expf(v[t].w - m_all);
        s += v[t].x + v[t].y + v[t].z + v[t].w;
    }
    #pragma unroll
    for (int o = 16; o; o >>= 1) s += __shfl_xor_sync(0xffffffffu, s, o);
    if ((threadIdx.x & 31) == 0) red[threadIdx.x >> 5] = s;
    __syncthreads();
    float s_all = 0.f;
    #pragma unroll
    for (int k = 0; k < 8; k++) s_all += red[k];
    const float inv = 1.0f / s_all;

    #pragma unroll
    for (int t = 0; t < 4; t++) {
        float4 o4 = make_float4(v[t].x * inv, v[t].y * inv, v[t].z * inv, v[t].w * inv);
        orow[threadIdx.x + t * 256] = o4;
    }
}

// ---------------------------------------------------------------------------
extern "C" void kernel_launch(void* const* d_in, const int* in_sizes, int n_in,
                              void* d_out, int out_size) {
    const float* out_state = (const float*)d_in[0];  // [2048, 2048]
    const float* history   = (const float*)d_in[1];  // [4096, 2048]
    const float* W         = (const float*)d_in[2];  // [2048, 2048]
    float* out = (float*)d_out;                      // [2048, 4096]
    // NOTE: b (d_in[3]) is unused: out_state.b is constant along each softmax
    // row and cancels exactly in softmax(scores, axis=-1).

    __half *osH, *osM, *wtH, *wtM, *hiH, *hiM, *tH, *tM;
    float *scores;
    void *qh, *hd, *d1;
    cudaGetSymbolAddress((void**)&osH, g_osH); cudaGetSymbolAddress((void**)&osM, g_osM);
    cudaGetSymbolAddress((void**)&wtH, g_wtH); cudaGetSymbolAddress((void**)&wtM, g_wtM);
    cudaGetSymbolAddress((void**)&hiH, g_hiH); cudaGetSymbolAddress((void**)&hiM, g_hiM);
    cudaGetSymbolAddress((void**)&tH, g_tH);   cudaGetSymbolAddress((void**)&tM, g_tM);
    cudaGetSymbolAddress((void**)&scores, g_scores);
    cudaGetSymbolAddress(&qh, g_qhead);
    cudaGetSymbolAddress(&hd, g_histdone);
    cudaGetSymbolAddress(&d1, g_done1);

    cudaFuncSetAttribute(fused_persistent, cudaFuncAttributeMaxDynamicSharedMemorySize,
                         (int)G_SMEM);

    // 0. reset work-queue state (graph-capturable async memsets)
    cudaMemsetAsync(qh, 0, sizeof(unsigned int));
    cudaMemsetAsync(hd, 0, sizeof(unsigned int));
    cudaMemsetAsync(d1, 0, 16 * sizeof(unsigned int));

    // 1. merged prep (one launch): split2(out_state) + transpose/scale/split(W)
    prep_kernel<<<8192, 256>>>(out_state, osH, osM, W, wtH, wtM);

    // 2. fused persistent: hist-split + gemm1 + gemm2 via work queue
    fused_persistent<<<148, 256, G_SMEM>>>(osH, osM, wtH, wtM, hiH, hiM,
                                           tH, tM, scores, history);

    // 3. softmax rows
    softmax_kernel<<<S_LEN, 256>>>(scores, out);
}

// round 16
// speedup vs baseline: 1.0011x; 1.0011x over previous
#include <cuda_runtime.h>
#include <cuda_fp16.h>
#include <cstdint>

constexpr int S_LEN = 2048;
constexpr int SEQ   = 4096;
constexpr int HID   = 2048;
constexpr int KDIM  = 2048;
constexpr float WSCALE = 64.0f;          // keep W's m-plane out of fp16 subnormals

// ---------------------------------------------------------------------------
// Scratch (__device__ globals; allocation-free rule)
// ---------------------------------------------------------------------------
__device__ __half g_osH[(size_t)S_LEN * HID];
__device__ __half g_osM[(size_t)S_LEN * HID];
__device__ __half g_wtH[(size_t)HID * HID];    // wt[k][h] = 64*W[h][k]
__device__ __half g_wtM[(size_t)HID * HID];
__device__ __half g_hiH[(size_t)SEQ * HID];
__device__ __half g_hiM[(size_t)SEQ * HID];
__device__ __half g_tH[(size_t)S_LEN * HID];   // planes of T' = 64*T
__device__ __half g_tM[(size_t)S_LEN * HID];
__device__ float g_scores[(size_t)S_LEN * SEQ];
// work-queue state (memset to 0 by host each launch)
__device__ unsigned int g_qhead;
__device__ unsigned int g_histdone;
__device__ unsigned int g_done1[16];

// ---------------------------------------------------------------------------
// PTX helpers (sm_80-baseline features only: legal on .target sm_103)
// ---------------------------------------------------------------------------
__device__ __forceinline__ uint32_t smem_to_u32(const void* p) {
    uint32_t a;
    asm("{ .reg .u64 t; cvta.to.shared.u64 t, %1; cvt.u32.u64 %0, t; }" : "=r"(a) : "l"(p));
    return a;
}
__device__ __forceinline__ void cp16(uint32_t dst, const void* src) {
    asm volatile("cp.async.cg.shared.global [%0], [%1], 16;" :: "r"(dst), "l"(src));
}
__device__ __forceinline__ void cp_commit() {
    asm volatile("cp.async.commit_group;" ::: "memory");
}
template <int N>
__device__ __forceinline__ void cp_wait() {
    asm volatile("cp.async.wait_group %0;" :: "n"(N) : "memory");
}
__device__ __forceinline__ void ldm4(uint32_t* r, uint32_t addr) {
    asm volatile("ldmatrix.sync.aligned.m8n8.x4.shared.b16 {%0,%1,%2,%3}, [%4];"
                 : "=r"(r[0]), "=r"(r[1]), "=r"(r[2]), "=r"(r[3]) : "r"(addr));
}
__device__ __forceinline__ void mma16816(float* d, const uint32_t* a, const uint32_t* b) {
    asm volatile(
        "mma.sync.aligned.m16n8k16.row.col.f32.f16.f16.f32 "
        "{%0,%1,%2,%3}, {%4,%5,%6,%7}, {%8,%9}, {%0,%1,%2,%3};"
        : "+f"(d[0]), "+f"(d[1]), "+f"(d[2]), "+f"(d[3])
        : "r"(a[0]), "r"(a[1]), "r"(a[2]), "r"(a[3]), "r"(b[0]), "r"(b[1]));
}

// ---------------------------------------------------------------------------
// 2-way fp16 split helpers
// ---------------------------------------------------------------------------
__device__ __forceinline__ void split2(float a, __half& h, __half& m) {
    h = __float2half_rn(a);
    float r = a - __half2float(h);
    m = __float2half_rn(r);
}

// Merged prep: blocks [0,4096) split out_state elementwise;
//              blocks [4096,8192) transpose+scale+split W.
__global__ __launch_bounds__(256) void prep_kernel(const float* __restrict__ os,
                                                   __half* __restrict__ osH,
                                                   __half* __restrict__ osM,
                                                   const float* __restrict__ W,
                                                   __half* __restrict__ wtH,
                                                   __half* __restrict__ wtM) {
    if (blockIdx.x < 4096) {
        const int i = blockIdx.x * 256 + threadIdx.x;      // < 2048*2048/4
        float4 v = reinterpret_cast<const float4*>(os)[i];
        __half h[4], m[4];
        split2(v.x, h[0], m[0]);
        split2(v.y, h[1], m[1]);
        split2(v.z, h[2], m[2]);
        split2(v.w, h[3], m[3]);
        reinterpret_cast<__half2*>(osH)[i * 2]     = __half2{h[0], h[1]};
        reinterpret_cast<__half2*>(osH)[i * 2 + 1] = __half2{h[2], h[3]};
        reinterpret_cast<__half2*>(osM)[i * 2]     = __half2{m[0], m[1]};
        reinterpret_cast<__half2*>(osM)[i * 2 + 1] = __half2{m[2], m[3]};
    } else {
        __shared__ float tile[32][33];
        const int bid = blockIdx.x - 4096;                 // 0..4095
        const int tx = threadIdx.x & 31;
        const int ty = threadIdx.x >> 5;
        const int k0 = (bid & 63) * 32;
        const int h0 = (bid >> 6) * 32;
        #pragma unroll
        for (int j = 0; j < 32; j += 8)
            tile[ty + j][tx] = W[(size_t)(h0 + ty + j) * HID + k0 + tx];
        __syncthreads();
        #pragma unroll
        for (int j = 0; j < 32; j += 8) {
            float a = tile[tx][ty + j] * WSCALE;
            __half h, m;
            split2(a, h, m);
            size_t o = (size_t)(k0 + ty + j) * HID + h0 + tx;
            wtH[o] = h; wtM[o] = m;
        }
    }
}

// ---------------------------------------------------------------------------
// HMMA emulated-fp32 GEMM tile body: C[128,256] = A @ B^T (fp16 2-way split,
// products hh, hm, mh).  8 warps (2M x 4N), warp tile 64x64, KC=64, 2-stage.
// __noinline__: exactly ONE code copy (~32KB) so the fused kernel's hot loop
// fits I$ (R13's dual-inline copy thrashed it).
//   epi==0: split C into fp16 h/m planes     epi==1: C = C*(1/WSCALE) f32
// ---------------------------------------------------------------------------
constexpr int KC    = 64;
constexpr int NCC   = KDIM / KC;               // 32 chunks
constexpr int ROWB  = 144;                     // 128B data + 16B pad
constexpr int G_NT  = 256;
constexpr int G_RT  = 2 * (128 + G_NT);        // 768 rows per stage
constexpr int G_STG = G_RT * ROWB;             // 110592
constexpr size_t G_SMEM = (size_t)2 * G_STG;   // 221184

__device__ __noinline__ void gemm_tile(
    uint32_t sb, int rowBase, int colBase,
    const __half* __restrict__ Ah, const __half* __restrict__ Am,
    const __half* __restrict__ Bh, const __half* __restrict__ Bm,
    int epi, float* __restrict__ outF,
    __half* __restrict__ Oh, __half* __restrict__ Om, int N) {
    const int tid  = threadIdx.x;
    const int lane = tid & 31;
    const int w    = tid >> 5;
    const int wm   = w & 1;        // 2 warps along M (64 rows)
    const int wn   = w >> 1;       // 4 warps along N (64 cols)

    uint32_t aOff[4], bOff[4];
    #pragma unroll
    for (int mt = 0; mt < 4; mt++)
        aOff[mt] = (uint32_t)((wm * 64 + mt * 16 + (lane & 15)) * ROWB + ((lane >> 4) << 4));
    #pragma unroll
    for (int nb = 0; nb < 4; nb++)
        bOff[nb] = (uint32_t)((wn * 64 + nb * 16 + (lane & 7) + ((lane >> 4) << 3)) * ROWB
                              + (((lane >> 3) & 1) << 4));

    float acc[4][8][4];
    #pragma unroll
    for (int mt = 0; mt < 4; mt++)
        #pragma unroll
        for (int nt = 0; nt < 8; nt++)
            #pragma unroll
            for (int q = 0; q < 4; q++) acc[mt][nt][q] = 0.f;

    const int lr = tid >> 2;        // 0..63
    const int lc = tid & 3;         // 16B chunk pair within 128B row
    auto load_stage = [&](int kc) {
        const uint32_t dst = sb + (uint32_t)(kc & 1) * G_STG;
        const char* sA[2] = {(const char*)(Ah + (size_t)(rowBase + lr) * KDIM + kc * KC),
                             (const char*)(Am + (size_t)(rowBase + lr) * KDIM + kc * KC)};
        const char* sB[2] = {(const char*)(Bh + (size_t)(colBase + lr) * KDIM + kc * KC),
                             (const char*)(Bm + (size_t)(colBase + lr) * KDIM + kc * KC)};
        #pragma unroll
        for (int p = 0; p < 2; p++) {
            #pragma unroll
            for (int j = 0; j < 2; j++) {          // A rows lr + 64j
                const int r = lr + j * 64;
                const char* src = sA[p] + (size_t)j * 64 * KDIM * 2;
                const uint32_t d = dst + (uint32_t)((p * 128 + r) * ROWB);
                cp16(d + lc * 16, src + lc * 16);
                cp16(d + lc * 16 + 64, src + lc * 16 + 64);
            }
            #pragma unroll
            for (int j = 0; j < 4; j++) {          // B rows lr + 64j
                const int r = lr + j * 64;
                const char* src = sB[p] + (size_t)j * 64 * KDIM * 2;
                const uint32_t d = dst + (uint32_t)((256 + p * G_NT + r) * ROWB);
                cp16(d + lc * 16, src + lc * 16);
                cp16(d + lc * 16 + 64, src + lc * 16 + 64);
            }
        }
    };

    load_stage(0); cp_commit();

    for (int kc = 0; kc < NCC; kc++) {
        cp_wait<0>();
        __syncthreads();
        if (kc + 1 < NCC) load_stage(kc + 1);
        cp_commit();

        const uint32_t base = sb + (uint32_t)(kc & 1) * G_STG;
        #pragma unroll
        for (int s = 0; s < 4; s++) {              // four k16 steps per chunk
            uint32_t af[2][4][4];
            uint32_t bf[2][4][4];
            #pragma unroll
            for (int pa = 0; pa < 2; pa++)
                #pragma unroll
                for (int mt = 0; mt < 4; mt++)
                    ldm4(af[pa][mt], base + (uint32_t)(pa * 128 * ROWB) + aOff[mt] + s * 32);
            #pragma unroll
            for (int pb = 0; pb < 2; pb++)
                #pragma unroll
                for (int nb = 0; nb < 4; nb++)
                    ldm4(bf[pb][nb],
                         base + (uint32_t)((256 + pb * G_NT) * ROWB) + bOff[nb] + s * 32);
            #pragma unroll
            for (int pb = 0; pb < 2; pb++)
                #pragma unroll
                for (int pa = 0; pa < 2; pa++) {
                    if (pa + pb > 1) continue;      // hh, mh, hm
                    #pragma unroll
                    for (int mt = 0; mt < 4; mt++)
                        #pragma unroll
                        for (int nt = 0; nt < 8; nt++)
                            mma16816(acc[mt][nt], af[pa][mt],
                                     &bf[pb][nt >> 1][(nt & 1) * 2]);
                }
        }
    }

    const int g   = lane >> 2;
    const int tig = lane & 3;
    constexpr float INVS = 1.0f / WSCALE;
    #pragma unroll
    for (int mt = 0; mt < 4; mt++) {
        #pragma unroll
        for (int hh = 0; hh < 2; hh++) {
            const int row = rowBase + wm * 64 + mt * 16 + g + hh * 8;
            #pragma unroll
            for (int nt = 0; nt < 8; nt++) {
                const int col = colBase + wn * 64 + nt * 8 + tig * 2;
                const float v0 = acc[mt][nt][hh * 2];
                const float v1 = acc[mt][nt][hh * 2 + 1];
                if (epi == 0) {
                    __half h0, m0, h1, m1;
                    split2(v0, h0, m0);
                    split2(v1, h1, m1);
                    const size_t o = (size_t)row * N + col;
                    *reinterpret_cast<__half2*>(Oh + o) = __half2{h0, h1};
                    *reinterpret_cast<__half2*>(Om + o) = __half2{m0, m1};
                } else {
                    *reinterpret_cast<float2*>(outF + (size_t)row * N + col) =
                        make_float2(v0 * INVS, v1 * INVS);
                }
            }
        }
    }
}

// ---------------------------------------------------------------------------
// Fused persistent kernel: 400 work items over 148 resident CTAs.
//   items [0,16):    history split chunks (producer for gemm2 B operand)
//   items [16,144):  gemm1 tiles  T' = out_state @ (64*W)  (rb=t>>3, cb=t&7)
//   items [144,400): gemm2 tiles  scores = (T' @ hist^T)/64 (rb=t>>4, cb=t&15)
// gemm2 items gate on done1[rb]==8 && histdone==16 (release: fence+atomicAdd).
// cp.async.cg loads bypass L1, so no stale-L1 hazard on cross-SM data.
// ---------------------------------------------------------------------------
constexpr unsigned N_HIST  = 16;
constexpr unsigned N_G1    = 128;
constexpr unsigned N_G2    = 256;
constexpr unsigned N_ITEMS = N_HIST + N_G1 + N_G2;   // 400

__global__ __launch_bounds__(256, 1)
void fused_persistent(const __half* __restrict__ osH, const __half* __restrict__ osM,
                      const __half* __restrict__ wtH, const __half* __restrict__ wtM,
                      __half* __restrict__ hiH, __half* __restrict__ hiM,
                      __half* __restrict__ tH, __half* __restrict__ tM,
                      float* __restrict__ scores,
                      const float* __restrict__ hist) {
    extern __shared__ char smem[];
    const uint32_t sb = smem_to_u32(smem);
    const int tid = threadIdx.x;
    __shared__ unsigned item_s;

    for (;;) {
        if (tid == 0) item_s = atomicAdd(&g_qhead, 1u);
        __syncthreads();
        const unsigned item = item_s;
        __syncthreads();                       // item_s safe to rewrite next iter
        if (item >= N_ITEMS) return;

        if (item < N_HIST) {
            // ---- history split chunk ----
            const int n4 = SEQ * HID / 4;
            for (int i = (int)item * 256 + tid; i < n4; i += (int)N_HIST * 256) {
                float4 v = reinterpret_cast<const float4*>(hist)[i];
                __half hh[4], mm[4];
                split2(v.x, hh[0], mm[0]);
                split2(v.y, hh[1], mm[1]);
                split2(v.z, hh[2], mm[2]);
                split2(v.w, hh[3], mm[3]);
                reinterpret_cast<__half2*>(hiH)[i * 2]     = __half2{hh[0], hh[1]};
                reinterpret_cast<__half2*>(hiH)[i * 2 + 1] = __half2{hh[2], hh[3]};
                reinterpret_cast<__half2*>(hiM)[i * 2]     = __half2{mm[0], mm[1]};
                reinterpret_cast<__half2*>(hiM)[i * 2 + 1] = __half2{mm[2], mm[3]};
            }
            __threadfence();
            __syncthreads();
            if (tid == 0) atomicAdd(&g_histdone, 1u);
            continue;
        }

        if (item < N_HIST + N_G1) {
            // ---- gemm1 tile: T' = out_state @ (64*W), epilogue splits T' ----
            const unsigned t = item - N_HIST;
            const int rb = (int)(t >> 3), cb = (int)(t & 7);
            gemm_tile(sb, rb * 128, cb * G_NT, osH, osM, wtH, wtM,
                      0, nullptr, tH, tM, HID);
            __threadfence();
            __syncthreads();
            if (tid == 0) atomicAdd(&g_done1[rb], 1u);
            continue;
        }

        // ---- gemm2 tile: scores = (T' @ hist^T)/64, gated on producers ----
        {
            const unsigned t = item - N_HIST - N_G1;
            const int rb = (int)(t >> 4), cb = (int)(t & 15);
            if (tid == 0) {
                while (atomicAdd(&g_done1[rb], 0u) < 8u ||
                       atomicAdd(&g_histdone, 0u) < N_HIST)
                    __nanosleep(200);
            }
            __syncthreads();
            __threadfence();                   // acquire before reading T/hist
            gemm_tile(sb, rb * 128, cb * G_NT, tH, tM, hiH, hiM,
                      1, scores, nullptr, nullptr, SEQ);
        }
    }
}

// ---------------------------------------------------------------------------
// Row softmax over 4096 columns (bias term out_state.b cancels in softmax)
// ---------------------------------------------------------------------------
__global__ __launch_bounds__(256) void softmax_kernel(const float* __restrict__ scores,
                                                      float* __restrict__ out) {
    const int i = blockIdx.x;
    const float4* row = reinterpret_cast<const float4*>(scores + (size_t)i * SEQ);
    float4* orow = reinterpret_cast<float4*>(out + (size_t)i * SEQ);

    float4 v[4];
    float m = -1e30f;
    #pragma unroll
    for (int t = 0; t < 4; t++) {
        v[t] = row[threadIdx.x + t * 256];
        m = fmaxf(m, fmaxf(fmaxf(v[t].x, v[t].y), fmaxf(v[t].z, v[t].w)));
    }
    __shared__ float red[8];
    #pragma unroll
    for (int o = 16; o; o >>= 1) m = fmaxf(m, __shfl_xor_sync(0xffffffffu, m, o));
    if ((threadIdx.x & 31) == 0) red[threadIdx.x >> 5] = m;
    __syncthreads();
    float m_all = red[0];
    #pragma unroll
    for (int k = 1; k < 8; k++) m_all = fmaxf(m_all, red[k]);
    __syncthreads();

    float s = 0.f;
    #pragma unroll
    for (int t = 0; t < 4; t++) {
        v[t].x = __expf(v[t].x - m_all);
        v[t].y = __expf(v[t].y - m_all);
        v[t].z = __expf(v[t].z - m_all);
        v[t].w = __expf(v[t].w - m_all);
        s += v[t].x + v[t].y + v[t].z + v[t].w;
    }
    #pragma unroll
    for (int o = 16; o; o >>= 1) s += __shfl_xor_sync(0xffffffffu, s, o);
    if ((threadIdx.x & 31) == 0) red[threadIdx.x >> 5] = s;
    __syncthreads();
    float s_all = 0.f;
    #pragma unroll
    for (int k = 0; k < 8; k++) s_all += red[k];
    const float inv = 1.0f / s_all;

    #pragma unroll
    for (int t = 0; t < 4; t++) {
        float4 o4 = make_float4(v[t].x * inv, v[t].y * inv, v[t].z * inv, v[t].w * inv);
        orow[threadIdx.x + t * 256] = o4;
    }
}

// ---------------------------------------------------------------------------
extern "C" void kernel_launch(void* const* d_in, const int* in_sizes, int n_in,
                              void* d_out, int out_size) {
    const float* out_state = (const float*)d_in[0];  // [2048, 2048]
    const float* history   = (const float*)d_in[1];  // [4096, 2048]
    const float* W         = (const float*)d_in[2];  // [2048, 2048]
    float* out = (float*)d_out;                      // [2048, 4096]
    // NOTE: b (d_in[3]) is unused: out_state.b is constant along each softmax
    // row and cancels exactly in softmax(scores, axis=-1).

    __half *osH, *osM, *wtH, *wtM, *hiH, *hiM, *tH, *tM;
    float *scores;
    void *qh, *hd, *d1;
    cudaGetSymbolAddress((void**)&osH, g_osH); cudaGetSymbolAddress((void**)&osM, g_osM);
    cudaGetSymbolAddress((void**)&wtH, g_wtH); cudaGetSymbolAddress((void**)&wtM, g_wtM);
    cudaGetSymbolAddress((void**)&hiH, g_hiH); cudaGetSymbolAddress((void**)&hiM, g_hiM);
    cudaGetSymbolAddress((void**)&tH, g_tH);   cudaGetSymbolAddress((void**)&tM, g_tM);
    cudaGetSymbolAddress((void**)&scores, g_scores);
    cudaGetSymbolAddress(&qh, g_qhead);
    cudaGetSymbolAddress(&hd, g_histdone);
    cudaGetSymbolAddress(&d1, g_done1);

    cudaFuncSetAttribute(fused_persistent, cudaFuncAttributeMaxDynamicSharedMemorySize,
                         (int)G_SMEM);

    // 0. reset work-queue state (graph-capturable async memsets)
    cudaMemsetAsync(qh, 0, sizeof(unsigned int));
    cudaMemsetAsync(hd, 0, sizeof(unsigned int));
    cudaMemsetAsync(d1, 0, 16 * sizeof(unsigned int));

    // 1. merged prep (one launch): split2(out_state) + transpose/scale/split(W)
    prep_kernel<<<8192, 256>>>(out_state, osH, osM, W, wtH, wtM);

    // 2. fused persistent: hist-split + gemm1 + gemm2 via work queue
    fused_persistent<<<148, 256, G_SMEM>>>(osH, osM, wtH, wtM, hiH, hiM,
                                           tH, tM, scores, history);

    // 3. softmax rows
    softmax_kernel<<<S_LEN, 256>>>(scores, out);
}

// round 17
// speedup vs baseline: 1.2117x; 1.2103x over previous
#include <cuda_runtime.h>
#include <cuda_fp16.h>
#include <cstdint>

constexpr int S_LEN = 2048;
constexpr int SEQ   = 4096;
constexpr int HID   = 2048;
constexpr int KDIM  = 2048;
constexpr float WSCALE = 64.0f;          // keep W's m-plane out of fp16 subnormals

// ---------------------------------------------------------------------------
// Scratch (__device__ globals; allocation-free rule)
// ---------------------------------------------------------------------------
__device__ __half g_osH[(size_t)S_LEN * HID];
__device__ __half g_osM[(size_t)S_LEN * HID];
__device__ __half g_wtH[(size_t)HID * HID];    // wt[k][h] = 64*W[h][k]
__device__ __half g_wtM[(size_t)HID * HID];
__device__ __half g_hiH[(size_t)SEQ * HID];
__device__ __half g_hiM[(size_t)SEQ * HID];
__device__ __half g_tH[(size_t)S_LEN * HID];   // planes of T' = 64*T
__device__ __half g_tM[(size_t)S_LEN * HID];
__device__ float g_scores[(size_t)S_LEN * SEQ];

// ---------------------------------------------------------------------------
// PTX helpers (sm_80-baseline features only: legal on .target sm_103)
// ---------------------------------------------------------------------------
__device__ __forceinline__ uint32_t smem_to_u32(const void* p) {
    uint32_t a;
    asm("{ .reg .u64 t; cvta.to.shared.u64 t, %1; cvt.u32.u64 %0, t; }" : "=r"(a) : "l"(p));
    return a;
}
__device__ __forceinline__ void cp16(uint32_t dst, const void* src) {
    asm volatile("cp.async.cg.shared.global [%0], [%1], 16;" :: "r"(dst), "l"(src));
}
__device__ __forceinline__ void cp_commit() {
    asm volatile("cp.async.commit_group;" ::: "memory");
}
template <int N>
__device__ __forceinline__ void cp_wait() {
    asm volatile("cp.async.wait_group %0;" :: "n"(N) : "memory");
}
__device__ __forceinline__ void ldm4(uint32_t* r, uint32_t addr) {
    asm volatile("ldmatrix.sync.aligned.m8n8.x4.shared.b16 {%0,%1,%2,%3}, [%4];"
                 : "=r"(r[0]), "=r"(r[1]), "=r"(r[2]), "=r"(r[3]) : "r"(addr));
}
__device__ __forceinline__ void mma16816(float* d, const uint32_t* a, const uint32_t* b) {
    asm volatile(
        "mma.sync.aligned.m16n8k16.row.col.f32.f16.f16.f32 "
        "{%0,%1,%2,%3}, {%4,%5,%6,%7}, {%8,%9}, {%0,%1,%2,%3};"
        : "+f"(d[0]), "+f"(d[1]), "+f"(d[2]), "+f"(d[3])
        : "r"(a[0]), "r"(a[1]), "r"(a[2]), "r"(a[3]), "r"(b[0]), "r"(b[1]));
}

// ---------------------------------------------------------------------------
// 2-way fp16 split helpers
// ---------------------------------------------------------------------------
__device__ __forceinline__ void split2(float a, __half& h, __half& m) {
    h = __float2half_rn(a);
    float r = a - __half2float(h);
    m = __float2half_rn(r);
}

// Merged prep: blocks [0,4096) split out_state elementwise;
//              blocks [4096,8192) transpose+scale+split W.
__global__ __launch_bounds__(256) void prep_kernel(const float* __restrict__ os,
                                                   __half* __restrict__ osH,
                                                   __half* __restrict__ osM,
                                                   const float* __restrict__ W,
                                                   __half* __restrict__ wtH,
                                                   __half* __restrict__ wtM) {
    if (blockIdx.x < 4096) {
        // --- split2 over out_state (float4-vectorized) ---
        const int i = blockIdx.x * 256 + threadIdx.x;      // < 2048*2048/4
        float4 v = reinterpret_cast<const float4*>(os)[i];
        __half h[4], m[4];
        split2(v.x, h[0], m[0]);
        split2(v.y, h[1], m[1]);
        split2(v.z, h[2], m[2]);
        split2(v.w, h[3], m[3]);
        reinterpret_cast<__half2*>(osH)[i * 2]     = __half2{h[0], h[1]};
        reinterpret_cast<__half2*>(osH)[i * 2 + 1] = __half2{h[2], h[3]};
        reinterpret_cast<__half2*>(osM)[i * 2]     = __half2{m[0], m[1]};
        reinterpret_cast<__half2*>(osM)[i * 2 + 1] = __half2{m[2], m[3]};
    } else {
        // --- W [h][k] -> wt[k][h] = 64*W[h][k] (32x32 smem transpose) ---
        __shared__ float tile[32][33];
        const int bid = blockIdx.x - 4096;                 // 0..4095
        const int tx = threadIdx.x & 31;
        const int ty = threadIdx.x >> 5;
        const int k0 = (bid & 63) * 32;
        const int h0 = (bid >> 6) * 32;
        #pragma unroll
        for (int j = 0; j < 32; j += 8)
            tile[ty + j][tx] = W[(size_t)(h0 + ty + j) * HID + k0 + tx];
        __syncthreads();
        #pragma unroll
        for (int j = 0; j < 32; j += 8) {
            float a = tile[tx][ty + j] * WSCALE;
            __half h, m;
            split2(a, h, m);
            size_t o = (size_t)(k0 + ty + j) * HID + h0 + tx;
            wtH[o] = h; wtM[o] = m;
        }
    }
}

// ---------------------------------------------------------------------------
// Unified HMMA emulated-fp32 GEMM: C[M,N] = A[M,K] @ B[N,K]^T (fp16 2-way split)
// Products: hh, hm, mh.  CTA tile 128x256, 8 warps (2M x 4N), warp tile 64x64.
// KC=64, 2-stage, occ 1.
//   EPI=0: split C into fp16 h/m planes
//   EPI=1: C = C*(1/WSCALE)   (bias term cancels in row-softmax)
//   HELP=1: blockIdx.y >= 16 are 16 helper CTAs running split2(history)
//           concurrently on SMs left idle by gemm1's 128 tiles.
// ---------------------------------------------------------------------------
constexpr int KC    = 64;
constexpr int NCC   = KDIM / KC;               // 32 chunks
constexpr int ROWB  = 144;                     // 128B data + 16B pad
constexpr int G_NT  = 256;
constexpr int G_RT  = 2 * (128 + G_NT);        // 768 rows per stage
constexpr int G_STG = G_RT * ROWB;             // 110592
constexpr size_t G_SMEM = (size_t)2 * G_STG;   // 221184

template <int EPI, int HELP>
__global__ __launch_bounds__(256, 1)
void gemm_mma(const __half* __restrict__ Ah, const __half* __restrict__ Am,
              const __half* __restrict__ Bh, const __half* __restrict__ Bm,
              float* __restrict__ outF, __half* __restrict__ Oh,
              __half* __restrict__ Om, int N,
              const float* __restrict__ hist, __half* __restrict__ hiH,
              __half* __restrict__ hiM) {
    const int tid = threadIdx.x;

    if (HELP && blockIdx.y >= 16) {
        // split2 over history, grid-strided across 16 helper CTAs
        const int h = (blockIdx.y - 16) * 8 + blockIdx.x;   // 0..15
        const int n4 = SEQ * HID / 4;
        for (int i = h * 256 + tid; i < n4; i += 16 * 256) {
            float4 v = reinterpret_cast<const float4*>(hist)[i];
            __half hh[4], mm[4];
            split2(v.x, hh[0], mm[0]);
            split2(v.y, hh[1], mm[1]);
            split2(v.z, hh[2], mm[2]);
            split2(v.w, hh[3], mm[3]);
            reinterpret_cast<__half2*>(hiH)[i * 2]     = __half2{hh[0], hh[1]};
            reinterpret_cast<__half2*>(hiH)[i * 2 + 1] = __half2{hh[2], hh[3]};
            reinterpret_cast<__half2*>(hiM)[i * 2]     = __half2{mm[0], mm[1]};
            reinterpret_cast<__half2*>(hiM)[i * 2 + 1] = __half2{mm[2], mm[3]};
        }
        return;
    }

    extern __shared__ char smem[];
    const uint32_t sb = smem_to_u32(smem);
    const int lane = tid & 31;
    const int w    = tid >> 5;
    const int wm   = w & 1;        // 2 warps along M (64 rows)
    const int wn   = w >> 1;       // 4 warps along N (64 cols)
    const int rowBase = blockIdx.y * 128;
    const int colBase = blockIdx.x * G_NT;

    uint32_t aOff[4], bOff[4];
    #pragma unroll
    for (int mt = 0; mt < 4; mt++)
        aOff[mt] = (uint32_t)((wm * 64 + mt * 16 + (lane & 15)) * ROWB + ((lane >> 4) << 4));
    #pragma unroll
    for (int nb = 0; nb < 4; nb++)
        bOff[nb] = (uint32_t)((wn * 64 + nb * 16 + (lane & 7) + ((lane >> 4) << 3)) * ROWB
                              + (((lane >> 3) & 1) << 4));

    float acc[4][8][4];
    #pragma unroll
    for (int mt = 0; mt < 4; mt++)
        #pragma unroll
        for (int nt = 0; nt < 8; nt++)
            #pragma unroll
            for (int q = 0; q < 4; q++) acc[mt][nt][q] = 0.f;

    const int lr = tid >> 2;        // 0..63
    const int lc = tid & 3;         // 16B chunk pair within 128B row
    auto load_stage = [&](int kc) {
        const uint32_t dst = sb + (uint32_t)(kc & 1) * G_STG;
        const char* sA[2] = {(const char*)(Ah + (size_t)(rowBase + lr) * KDIM + kc * KC),
                             (const char*)(Am + (size_t)(rowBase + lr) * KDIM + kc * KC)};
        const char* sB[2] = {(const char*)(Bh + (size_t)(colBase + lr) * KDIM + kc * KC),
                             (const char*)(Bm + (size_t)(colBase + lr) * KDIM + kc * KC)};
        #pragma unroll
        for (int p = 0; p < 2; p++) {
            #pragma unroll
            for (int j = 0; j < 2; j++) {          // A rows lr + 64j
                const int r = lr + j * 64;
                const char* src = sA[p] + (size_t)j * 64 * KDIM * 2;
                const uint32_t d = dst + (uint32_t)((p * 128 + r) * ROWB);
                cp16(d + lc * 16, src + lc * 16);
                cp16(d + lc * 16 + 64, src + lc * 16 + 64);
            }
            #pragma unroll
            for (int j = 0; j < 4; j++) {          // B rows lr + 64j
                const int r = lr + j * 64;
                const char* src = sB[p] + (size_t)j * 64 * KDIM * 2;
                const uint32_t d = dst + (uint32_t)((256 + p * G_NT + r) * ROWB);
                cp16(d + lc * 16, src + lc * 16);
                cp16(d + lc * 16 + 64, src + lc * 16 + 64);
            }
        }
    };

    load_stage(0); cp_commit();

    for (int kc = 0; kc < NCC; kc++) {
        cp_wait<0>();
        __syncthreads();
        if (kc + 1 < NCC) load_stage(kc + 1);
        cp_commit();

        const uint32_t base = sb + (uint32_t)(kc & 1) * G_STG;
        #pragma unroll
        for (int s = 0; s < 4; s++) {              // four k16 steps per chunk
            uint32_t af[2][4][4];
            uint32_t bf[2][4][4];
            #pragma unroll
            for (int pa = 0; pa < 2; pa++)
                #pragma unroll
                for (int mt = 0; mt < 4; mt++)
                    ldm4(af[pa][mt], base + (uint32_t)(pa * 128 * ROWB) + aOff[mt] + s * 32);
            #pragma unroll
            for (int pb = 0; pb < 2; pb++)
                #pragma unroll
                for (int nb = 0; nb < 4; nb++)
                    ldm4(bf[pb][nb],
                         base + (uint32_t)((256 + pb * G_NT) * ROWB) + bOff[nb] + s * 32);
            #pragma unroll
            for (int pb = 0; pb < 2; pb++)
                #pragma unroll
                for (int pa = 0; pa < 2; pa++) {
                    if (pa + pb > 1) continue;      // hh, mh, hm
                    #pragma unroll
                    for (int mt = 0; mt < 4; mt++)
                        #pragma unroll
                        for (int nt = 0; nt < 8; nt++)
                            mma16816(acc[mt][nt], af[pa][mt],
                                     &bf[pb][nt >> 1][(nt & 1) * 2]);
                }
        }
    }

    const int g   = lane >> 2;
    const int tig = lane & 3;
    constexpr float INVS = 1.0f / WSCALE;
    #pragma unroll
    for (int mt = 0; mt < 4; mt++) {
        #pragma unroll
        for (int hh = 0; hh < 2; hh++) {
            const int row = rowBase + wm * 64 + mt * 16 + g + hh * 8;
            #pragma unroll
            for (int nt = 0; nt < 8; nt++) {
                const int col = colBase + wn * 64 + nt * 8 + tig * 2;
                const float v0 = acc[mt][nt][hh * 2];
                const float v1 = acc[mt][nt][hh * 2 + 1];
                if (EPI == 0) {
                    __half h0, m0, h1, m1;
                    split2(v0, h0, m0);
                    split2(v1, h1, m1);
                    const size_t o = (size_t)row * N + col;
                    *reinterpret_cast<__half2*>(Oh + o) = __half2{h0, h1};
                    *reinterpret_cast<__half2*>(Om + o) = __half2{m0, m1};
                } else {
                    *reinterpret_cast<float2*>(outF + (size_t)row * N + col) =
                        make_float2(v0 * INVS, v1 * INVS);
                }
            }
        }
    }
}

// ---------------------------------------------------------------------------
// Row softmax over 4096 columns (bias term out_state.b cancels in softmax)
// ---------------------------------------------------------------------------
__global__ __launch_bounds__(256) void softmax_kernel(const float* __restrict__ scores,
                                                      float* __restrict__ out) {
    const int i = blockIdx.x;
    const float4* row = reinterpret_cast<const float4*>(scores + (size_t)i * SEQ);
    float4* orow = reinterpret_cast<float4*>(out + (size_t)i * SEQ);

    float4 v[4];
    float m = -1e30f;
    #pragma unroll
    for (int t = 0; t < 4; t++) {
        v[t] = row[threadIdx.x + t * 256];
        m = fmaxf(m, fmaxf(fmaxf(v[t].x, v[t].y), fmaxf(v[t].z, v[t].w)));
    }
    __shared__ float red[8];
    #pragma unroll
    for (int o = 16; o; o >>= 1) m = fmaxf(m, __shfl_xor_sync(0xffffffffu, m, o));
    if ((threadIdx.x & 31) == 0) red[threadIdx.x >> 5] = m;
    __syncthreads();
    float m_all = red[0];
    #pragma unroll
    for (int k = 1; k < 8; k++) m_all = fmaxf(m_all, red[k]);
    __syncthreads();

    float s = 0.f;
    #pragma unroll
    for (int t = 0; t < 4; t++) {
        v[t].x = __expf(v[t].x - m_all);
        v[t].y = __expf(v[t].y - m_all);
        v[t].z = __expf(v[t].z - m_all);
        v[t].w = __expf(v[t].w - m_all);
        s += v[t].x + v[t].y + v[t].z + v[t].w;
    }
    #pragma unroll
    for (int o = 16; o; o >>= 1) s += __shfl_xor_sync(0xffffffffu, s, o);
    if ((threadIdx.x & 31) == 0) red[threadIdx.x >> 5] = s;
    __syncthreads();
    float s_all = 0.f;
    #pragma unroll
    for (int k = 0; k < 8; k++) s_all += red[k];
    const float inv = 1.0f / s_all;

    #pragma unroll
    for (int t = 0; t < 4; t++) {
        float4 o4 = make_float4(v[t].x * inv, v[t].y * inv, v[t].z * inv, v[t].w * inv);
        orow[threadIdx.x + t * 256] = o4;
    }
}

// ---------------------------------------------------------------------------
extern "C" void kernel_launch(void* const* d_in, const int* in_sizes, int n_in,
                              void* d_out, int out_size) {
    const float* out_state = (const float*)d_in[0];  // [2048, 2048]
    const float* history   = (const float*)d_in[1];  // [4096, 2048]
    const float* W         = (const float*)d_in[2];  // [2048, 2048]
    float* out = (float*)d_out;                      // [2048, 4096]
    // NOTE: b (d_in[3]) is unused: out_state.b is constant along each softmax
    // row and cancels exactly in softmax(scores, axis=-1).

    __half *osH, *osM, *wtH, *wtM, *hiH, *hiM, *tH, *tM;
    float *scores;
    cudaGetSymbolAddress((void**)&osH, g_osH); cudaGetSymbolAddress((void**)&osM, g_osM);
    cudaGetSymbolAddress((void**)&wtH, g_wtH); cudaGetSymbolAddress((void**)&wtM, g_wtM);
    cudaGetSymbolAddress((void**)&hiH, g_hiH); cudaGetSymbolAddress((void**)&hiM, g_hiM);
    cudaGetSymbolAddress((void**)&tH, g_tH);   cudaGetSymbolAddress((void**)&tM, g_tM);
    cudaGetSymbolAddress((void**)&scores, g_scores);

    cudaFuncSetAttribute(gemm_mma<0, 1>, cudaFuncAttributeMaxDynamicSharedMemorySize,
                         (int)G_SMEM);
    cudaFuncSetAttribute(gemm_mma<1, 0>, cudaFuncAttributeMaxDynamicSharedMemorySize,
                         (int)G_SMEM);

    // 1. merged prep (one launch): split2(out_state) + transpose/scale/split(W)
    prep_kernel<<<8192, 256>>>(out_state, osH, osM, W, wtH, wtM);

    // 2. T' = out_state @ (64*W) (128 gemm CTAs) + 16 helper CTAs doing
    //    split2(history) on otherwise-idle SMs
    gemm_mma<0, 1><<<dim3(HID / G_NT, 18), 256, G_SMEM>>>(
        osH, osM, wtH, wtM, nullptr, tH, tM, HID,
        history, hiH, hiM);

    // 3. scores = (T' @ history^T)/64
    gemm_mma<1, 0><<<dim3(SEQ / G_NT, S_LEN / 128), 256, G_SMEM>>>(
        tH, tM, hiH, hiM, scores, nullptr, nullptr, SEQ,
        nullptr, nullptr, nullptr);

    // 4. softmax rows
    softmax_kernel<<<S_LEN, 256>>>(scores, out);
}